// round 1
// baseline (speedup 1.0000x reference)
#include <cuda_runtime.h>
#include <math.h>

#define SEQ    4096
#define DIM    1024
#define HEADS  16
#define DHEAD  64
#define INNER  1024      // HEADS*DHEAD
#define QKV_N  3072      // 3*INNER
#define LN_EPS 1e-6f
#define ATT_SCALE 0.03125f   // DIM^-0.5 = 1/32  (module scales by dim_in, not dim_head)

// ---------------------------------------------------------------------------
// Scratch (static device globals; no runtime allocation allowed)
// ---------------------------------------------------------------------------
__device__ float g_xn  [SEQ * DIM];     // LayerNorm output
__device__ float g_qkv [SEQ * QKV_N];   // QKV projection
__device__ float g_attn[SEQ * INNER];   // attention output (pre out-proj)

// ---------------------------------------------------------------------------
// Kernel 1: LayerNorm. One block (256 threads) per row of 1024 floats.
// ---------------------------------------------------------------------------
__global__ void __launch_bounds__(256) ln_kernel(
    const float* __restrict__ x, const float* __restrict__ g,
    const float* __restrict__ b, float* __restrict__ o)
{
    const int row = blockIdx.x;
    const int t   = threadIdx.x;
    const float4* xr = (const float4*)(x + (size_t)row * DIM);
    float4 v = xr[t];                              // 4 floats per thread

    float s  = v.x + v.y + v.z + v.w;
    float s2 = v.x*v.x + v.y*v.y + v.z*v.z + v.w*v.w;
    #pragma unroll
    for (int off = 16; off > 0; off >>= 1) {
        s  += __shfl_down_sync(0xffffffffu, s,  off);
        s2 += __shfl_down_sync(0xffffffffu, s2, off);
    }
    __shared__ float ss[8], ss2[8];
    const int w = t >> 5, ln = t & 31;
    if (ln == 0) { ss[w] = s; ss2[w] = s2; }
    __syncthreads();
    if (t == 0) {
        float a = 0.f, a2 = 0.f;
        #pragma unroll
        for (int i = 0; i < 8; i++) { a += ss[i]; a2 += ss2[i]; }
        ss[0] = a; ss2[0] = a2;
    }
    __syncthreads();
    const float mean = ss[0] * (1.0f / DIM);
    const float var  = ss2[0] * (1.0f / DIM) - mean * mean;
    const float rstd = rsqrtf(var + LN_EPS);

    float4 gv = ((const float4*)g)[t];
    float4 bv = ((const float4*)b)[t];
    float4 ov;
    ov.x = (v.x - mean) * rstd * gv.x + bv.x;
    ov.y = (v.y - mean) * rstd * gv.y + bv.y;
    ov.z = (v.z - mean) * rstd * gv.z + bv.z;
    ov.w = (v.w - mean) * rstd * gv.w + bv.w;
    ((float4*)(o + (size_t)row * DIM))[t] = ov;
}

// ---------------------------------------------------------------------------
// Kernel 2: SIMT fp32 GEMM  C[M,N] = A[M,K] @ B[K,N] (+ bias)
// 128x128 block tile, BK=16, 256 threads, 8x8 microtile per thread.
// All dims here are multiples of 128/16 — no edge handling.
// ---------------------------------------------------------------------------
__global__ void __launch_bounds__(256) sgemm_kernel(
    const float* __restrict__ A, const float* __restrict__ B,
    float* __restrict__ C, int M, int N, int K,
    const float* __restrict__ bias)
{
    __shared__ float As[16][132];   // A tile stored transposed [k][m], padded
    __shared__ float Bs[16][128];   // B tile natural [k][n]

    const int bx = blockIdx.x, by = blockIdx.y;
    const int tid = threadIdx.x;
    const int tx = tid & 15, ty = tid >> 4;

    const float* Ab = A + (size_t)(by * 128) * K;
    const float* Bb = B + bx * 128;

    // load assignments
    const int arow = tid >> 1;          // 0..127
    const int acol = (tid & 1) * 8;     // 0 or 8
    const int brow = tid >> 4;          // 0..15
    const int bcol = (tid & 15) * 8;    // 0..120

    float acc[8][8];
    #pragma unroll
    for (int i = 0; i < 8; i++)
        #pragma unroll
        for (int j = 0; j < 8; j++) acc[i][j] = 0.f;

    for (int k0 = 0; k0 < K; k0 += 16) {
        float4 a0 = *(const float4*)(Ab + (size_t)arow * K + k0 + acol);
        float4 a1 = *(const float4*)(Ab + (size_t)arow * K + k0 + acol + 4);
        float4 b0 = *(const float4*)(Bb + (size_t)(k0 + brow) * N + bcol);
        float4 b1 = *(const float4*)(Bb + (size_t)(k0 + brow) * N + bcol + 4);
        __syncthreads();   // prior tile fully consumed before overwrite
        As[acol+0][arow] = a0.x; As[acol+1][arow] = a0.y;
        As[acol+2][arow] = a0.z; As[acol+3][arow] = a0.w;
        As[acol+4][arow] = a1.x; As[acol+5][arow] = a1.y;
        As[acol+6][arow] = a1.z; As[acol+7][arow] = a1.w;
        *(float4*)&Bs[brow][bcol]     = b0;
        *(float4*)&Bs[brow][bcol + 4] = b1;
        __syncthreads();

        #pragma unroll
        for (int k = 0; k < 16; k++) {
            float a[8], bb[8];
            *(float4*)(a)      = *(const float4*)&As[k][ty * 8];
            *(float4*)(a + 4)  = *(const float4*)&As[k][ty * 8 + 4];
            *(float4*)(bb)     = *(const float4*)&Bs[k][tx * 8];
            *(float4*)(bb + 4) = *(const float4*)&Bs[k][tx * 8 + 4];
            #pragma unroll
            for (int i = 0; i < 8; i++)
                #pragma unroll
                for (int j = 0; j < 8; j++)
                    acc[i][j] += a[i] * bb[j];
        }
    }

    float bv[8];
    #pragma unroll
    for (int j = 0; j < 8; j++)
        bv[j] = bias ? bias[bx * 128 + tx * 8 + j] : 0.f;

    #pragma unroll
    for (int i = 0; i < 8; i++) {
        float* crow = C + (size_t)(by * 128 + ty * 8 + i) * N + bx * 128 + tx * 8;
        float4 o0, o1;
        o0.x = acc[i][0] + bv[0]; o0.y = acc[i][1] + bv[1];
        o0.z = acc[i][2] + bv[2]; o0.w = acc[i][3] + bv[3];
        o1.x = acc[i][4] + bv[4]; o1.y = acc[i][5] + bv[5];
        o1.z = acc[i][6] + bv[6]; o1.w = acc[i][7] + bv[7];
        *(float4*)(crow)     = o0;
        *(float4*)(crow + 4) = o1;
    }
}

// ---------------------------------------------------------------------------
// Kernel 3: fused flash-style attention, one block per (head, 64-query tile).
// Bi=64 queries, Bj=32 keys/tile, d=64. 256 threads = 16x16 grid.
// Online softmax; row stats reduced across the 16 tx lanes via shuffles.
// ---------------------------------------------------------------------------
__global__ void __launch_bounds__(256) attn_kernel(
    const float* __restrict__ qkv, float* __restrict__ out)
{
    __shared__ float Qs[64][68];   // transposed: Qs[k][r]
    __shared__ float Ks[64][36];   // transposed: Ks[k][j]
    __shared__ float Vs[32][68];   // natural:    Vs[j][d]
    __shared__ float Ps[32][68];   // transposed P: Ps[j][r]

    const int h  = blockIdx.y;
    const int i0 = blockIdx.x * 64;
    const int tid = threadIdx.x;
    const int tx = tid & 15, ty = tid >> 4;

    const float* qbase = qkv + h * DHEAD;
    const float* kbase = qkv + INNER + h * DHEAD;
    const float* vbase = qkv + 2 * INNER + h * DHEAD;

    // ---- load Q tile (64x64) transposed into Qs ----
    {
        const int r  = tid >> 2;            // 0..63
        const int c0 = (tid & 3) * 16;      // 0,16,32,48
        const float* src = qbase + (size_t)(i0 + r) * QKV_N + c0;
        #pragma unroll
        for (int c4 = 0; c4 < 16; c4 += 4) {
            float4 v = *(const float4*)(src + c4);
            Qs[c0 + c4 + 0][r] = v.x; Qs[c0 + c4 + 1][r] = v.y;
            Qs[c0 + c4 + 2][r] = v.z; Qs[c0 + c4 + 3][r] = v.w;
        }
    }

    float m[4], l[4], acc[4][4];
    #pragma unroll
    for (int rr = 0; rr < 4; rr++) {
        m[rr] = -1e30f; l[rr] = 0.f;
        #pragma unroll
        for (int dd = 0; dd < 4; dd++) acc[rr][dd] = 0.f;
    }

    const int r0  = ty * 4;   // 4 query rows
    const int d0  = tx * 4;   // 4 output dims
    const int jc0 = tx * 2;   // 2 key columns in S

    for (int j0 = 0; j0 < SEQ; j0 += 32) {
        __syncthreads();  // prior-tile reads of Ks/Vs/Ps done (also covers Q store, iter 0)

        // ---- load K (transposed) and V (natural) tiles ----
        {
            const int j  = tid >> 3;           // 0..31
            const int c0 = (tid & 7) * 8;      // 0..56
            const float* ksrc = kbase + (size_t)(j0 + j) * QKV_N + c0;
            float4 k0v = *(const float4*)(ksrc);
            float4 k1v = *(const float4*)(ksrc + 4);
            Ks[c0 + 0][j] = k0v.x; Ks[c0 + 1][j] = k0v.y;
            Ks[c0 + 2][j] = k0v.z; Ks[c0 + 3][j] = k0v.w;
            Ks[c0 + 4][j] = k1v.x; Ks[c0 + 5][j] = k1v.y;
            Ks[c0 + 6][j] = k1v.z; Ks[c0 + 7][j] = k1v.w;
            const float* vsrc = vbase + (size_t)(j0 + j) * QKV_N + c0;
            *(float4*)&Vs[j][c0]     = *(const float4*)(vsrc);
            *(float4*)&Vs[j][c0 + 4] = *(const float4*)(vsrc + 4);
        }
        __syncthreads();

        // ---- S tile: s[rr][jc] = (Q K^T)*scale ----
        float s[4][2];
        #pragma unroll
        for (int rr = 0; rr < 4; rr++) { s[rr][0] = 0.f; s[rr][1] = 0.f; }
        #pragma unroll 8
        for (int k = 0; k < 64; k++) {
            float4 q  = *(const float4*)&Qs[k][r0];
            float2 kk = *(const float2*)&Ks[k][jc0];
            s[0][0] += q.x * kk.x; s[0][1] += q.x * kk.y;
            s[1][0] += q.y * kk.x; s[1][1] += q.y * kk.y;
            s[2][0] += q.z * kk.x; s[2][1] += q.z * kk.y;
            s[3][0] += q.w * kk.x; s[3][1] += q.w * kk.y;
        }

        // ---- online softmax (reduce across 16 tx lanes via xor-shuffles) ----
        #pragma unroll
        for (int rr = 0; rr < 4; rr++) {
            s[rr][0] *= ATT_SCALE; s[rr][1] *= ATT_SCALE;
            float pm = fmaxf(s[rr][0], s[rr][1]);
            #pragma unroll
            for (int off = 8; off > 0; off >>= 1)
                pm = fmaxf(pm, __shfl_xor_sync(0xffffffffu, pm, off));
            const float mn = fmaxf(m[rr], pm);
            const float al = __expf(m[rr] - mn);
            const float p0 = __expf(s[rr][0] - mn);
            const float p1 = __expf(s[rr][1] - mn);
            Ps[jc0][r0 + rr]     = p0;
            Ps[jc0 + 1][r0 + rr] = p1;
            float ps = p0 + p1;
            #pragma unroll
            for (int off = 8; off > 0; off >>= 1)
                ps += __shfl_xor_sync(0xffffffffu, ps, off);
            l[rr] = l[rr] * al + ps;
            m[rr] = mn;
            acc[rr][0] *= al; acc[rr][1] *= al;
            acc[rr][2] *= al; acc[rr][3] *= al;
        }
        __syncthreads();  // Ps visible to all

        // ---- O += P @ V ----
        #pragma unroll 8
        for (int jj = 0; jj < 32; jj++) {
            float4 p = *(const float4*)&Ps[jj][r0];
            float4 v = *(const float4*)&Vs[jj][d0];
            acc[0][0] += p.x * v.x; acc[0][1] += p.x * v.y;
            acc[0][2] += p.x * v.z; acc[0][3] += p.x * v.w;
            acc[1][0] += p.y * v.x; acc[1][1] += p.y * v.y;
            acc[1][2] += p.y * v.z; acc[1][3] += p.y * v.w;
            acc[2][0] += p.z * v.x; acc[2][1] += p.z * v.y;
            acc[2][2] += p.z * v.z; acc[2][3] += p.z * v.w;
            acc[3][0] += p.w * v.x; acc[3][1] += p.w * v.y;
            acc[3][2] += p.w * v.z; acc[3][3] += p.w * v.w;
        }
    }

    // ---- epilogue: normalize and store to [i, h*64 + d] ----
    #pragma unroll
    for (int rr = 0; rr < 4; rr++) {
        const float inv = 1.0f / l[rr];
        float4 o;
        o.x = acc[rr][0] * inv; o.y = acc[rr][1] * inv;
        o.z = acc[rr][2] * inv; o.w = acc[rr][3] * inv;
        *(float4*)(out + (size_t)(i0 + r0 + rr) * INNER + h * DHEAD + d0) = o;
    }
}

// ---------------------------------------------------------------------------
// Launcher
// ---------------------------------------------------------------------------
extern "C" void kernel_launch(void* const* d_in, const int* in_sizes, int n_in,
                              void* d_out, int out_size)
{
    const float* x      = (const float*)d_in[0];
    const float* ln_s   = (const float*)d_in[1];
    const float* ln_b   = (const float*)d_in[2];
    const float* w_qkv  = (const float*)d_in[3];
    const float* w_out  = (const float*)d_in[4];
    const float* b_out  = (const float*)d_in[5];
    float* out = (float*)d_out;

    float *xn, *qkvbuf, *attnbuf;
    cudaGetSymbolAddress((void**)&xn,      g_xn);
    cudaGetSymbolAddress((void**)&qkvbuf,  g_qkv);
    cudaGetSymbolAddress((void**)&attnbuf, g_attn);

    // 1) LayerNorm
    ln_kernel<<<SEQ, 256>>>(x, ln_s, ln_b, xn);

    // 2) QKV projection: [4096,1024] @ [1024,3072]
    dim3 g1(QKV_N / 128, SEQ / 128);
    sgemm_kernel<<<g1, 256>>>(xn, w_qkv, qkvbuf, SEQ, QKV_N, DIM, nullptr);

    // 3) fused multi-head attention
    dim3 g2(SEQ / 64, HEADS);
    attn_kernel<<<g2, 256>>>(qkvbuf, attnbuf);

    // 4) output projection + bias: [4096,1024] @ [1024,1024] + b
    dim3 g3(DIM / 128, SEQ / 128);
    sgemm_kernel<<<g3, 256>>>(attnbuf, w_out, out, SEQ, DIM, DIM, b_out);
}